// round 13
// baseline (speedup 1.0000x reference)
#include <cuda_runtime.h>
#include <cstdint>

#define NRAYS 16384
#define NFINE 128

typedef unsigned long long u64;

// ---- fast transcendentals ----
__device__ __forceinline__ float fexp(float x)   { return __expf(x); }
__device__ __forceinline__ float fexp10(float x) { return __exp10f(x); }
__device__ __forceinline__ float frsqrt_approx(float x) {
    float r; asm("rsqrt.approx.f32 %0, %1;" : "=f"(r) : "f"(x)); return r;
}
__device__ __forceinline__ float fsigmoid(float x) {
    return __fdividef(1.0f, 1.0f + __expf(-x));
}
__device__ __forceinline__ float fsoftplus(float x) {
    return fmaxf(x, 0.0f) + __logf(1.0f + __expf(-fabsf(x)));
}
__device__ __forceinline__ uint32_t f2tf32(float x) {
    uint32_t r; asm("cvt.rna.tf32.f32 %0, %1;" : "=r"(r) : "f"(x)); return r;
}
// m16n8k8 tf32 HMMA (standard PTX, sm_80+; runs on sm_103 tensor pipe)
__device__ __forceinline__ void mma_tf32(float* d,
    uint32_t a0, uint32_t a1, uint32_t a2, uint32_t a3,
    uint32_t b0, uint32_t b1)
{
    asm volatile(
        "mma.sync.aligned.m16n8k8.row.col.f32.tf32.tf32.f32 "
        "{%0,%1,%2,%3}, {%4,%5,%6,%7}, {%8,%9}, {%0,%1,%2,%3};"
        : "+f"(d[0]), "+f"(d[1]), "+f"(d[2]), "+f"(d[3])
        : "r"(a0), "r"(a1), "r"(a2), "r"(a3), "r"(b0), "r"(b1));
}

// exact z-grid helpers
__device__ __forceinline__ float zlog_c(int i) {
    return (i < 128) ? (float)(i - 128) * 0.0078125f : (float)(i - 128) * 0.015625f;
}
__device__ __forceinline__ float zmid_c(int i) {
    return 0.5f * (zlog_c(i) + zlog_c(i + 1));
}
__device__ __forceinline__ unsigned rotl32(unsigned x, int r) {
    return __funnelshift_l(x, x, r);
}

// JAX threefry2x32, key=(0,42), partitionable counter mode: bits = out0^out1
__device__ __forceinline__ float tf_uniform(unsigned idx) {
    unsigned x0 = 0u, x1 = idx;
    const unsigned ks1 = 42u;
    const unsigned ks2 = 42u ^ 0x1BD11BDAu;
    x0 += 0u; x1 += ks1;
#define TF_RND(R) { x0 += x1; x1 = rotl32(x1, R); x1 ^= x0; }
    TF_RND(13) TF_RND(15) TF_RND(26) TF_RND(6)
    x0 += ks1; x1 += ks2 + 1u;
    TF_RND(17) TF_RND(29) TF_RND(16) TF_RND(24)
    x0 += ks2; x1 += 0u + 2u;
    TF_RND(13) TF_RND(15) TF_RND(26) TF_RND(6)
    x0 += 0u; x1 += ks1 + 3u;
    TF_RND(17) TF_RND(29) TF_RND(16) TF_RND(24)
    x0 += ks1; x1 += ks2 + 4u;
    TF_RND(13) TF_RND(15) TF_RND(26) TF_RND(6)
    x0 += ks2; x1 += 0u + 5u;
#undef TF_RND
    unsigned bits = x0 ^ x1;
    return __uint_as_float((bits >> 9) | 0x3f800000u) - 1.0f;
}

__device__ __forceinline__ void mip_scale(float& x, float& y, float& z) {
    float d2 = x * x + y * y + z * z;
    float r  = frsqrt_approx(d2);
    float d  = d2 * r;
    if (d > 1.0f) {
        float s = (2.0f - r) * r;
        x *= s; y *= s; z *= s;
    }
}

__global__ void __launch_bounds__(128, 4) nerf_fused(
    const float* __restrict__ gh, const float* __restrict__ gw,
    const float* __restrict__ gK, const float* __restrict__ gE,
    const float* __restrict__ gbg,
    const float* __restrict__ gWd1, const float* __restrict__ gbd1,
    const float* __restrict__ gWd2, const float* __restrict__ gbd2,
    const float* __restrict__ gWc1, const float* __restrict__ gbc1,
    const float* __restrict__ gWc2, const float* __restrict__ gbc2,
    float* __restrict__ oImg, float* __restrict__ oW,
    float* __restrict__ oZ, float* __restrict__ oInv)
{
    __shared__ float4 sWd1p[32];            // (w0,w1,w2,b) per hidden c
    __shared__ float  sWd2[32];
    __shared__ __align__(16) float sWc2c[3][32];
    __shared__ float  sInit[4][32];         // per-ray bc1 + dir terms
    __shared__ uint2  sBfrag[4][4][32];     // b-frags [kt][nt][lane] = (b0,b1) tf32
    __shared__ float  sCdf[4][256];
    __shared__ float  sZc[192];             // exp10(zlog_c(i)) — ray-invariant
    __shared__ __align__(16) float sT[4][1024];  // per-warp T tile

    const int tid  = threadIdx.x;
    const int lane = tid & 31;
    const int warp = tid >> 5;
    const int gid  = lane >> 2;
    const int tig  = lane & 3;
    const int ray  = (blockIdx.x << 2) + warp;

    // ---- stage weights + B fragments + z-table ----
    if (tid < 32) {
        sWd1p[tid] = make_float4(gWd1[tid], gWd1[32 + tid], gWd1[64 + tid], gbd1[tid]);
        sWd2[tid]  = gWd2[tid];
        sWc2c[0][tid] = gWc2[tid * 3 + 0];
        sWc2c[1][tid] = gWc2[tid * 3 + 1];
        sWc2c[2][tid] = gWc2[tid * 3 + 2];
    }
    for (int i = tid; i < 512; i += 128) {
        int kt = i >> 7, nt = (i >> 5) & 3, l = i & 31;
        int lt = l & 3, lg = l >> 2;
        int c0 = 8 * kt + lt, j = 8 * nt + lg;
        sBfrag[kt][nt][l] = make_uint2(f2tf32(gWc1[c0 * 32 + j]),
                                       f2tf32(gWc1[(c0 + 4) * 32 + j]));
    }
    for (int i = tid; i < 192; i += 128) sZc[i] = fexp10(zlog_c(i));
    __syncthreads();

    // ---- ray setup ----
    float k00 = gK[0], k01 = gK[1], k02 = gK[2];
    float k10 = gK[3], k11 = gK[4], k12 = gK[5];
    float k20 = gK[6], k21 = gK[7], k22 = gK[8];
    float det = k00 * (k11 * k22 - k12 * k21)
              + k01 * (k12 * k20 - k10 * k22)
              + k02 * (k10 * k21 - k11 * k20);
    float id = 1.0f / det;
    float i00 = (k11 * k22 - k12 * k21) * id, i01 = (k02 * k21 - k01 * k22) * id, i02 = (k01 * k12 - k02 * k11) * id;
    float i10 = (k12 * k20 - k10 * k22) * id, i11 = (k00 * k22 - k02 * k20) * id, i12 = (k02 * k10 - k00 * k12) * id;
    float i20 = (k10 * k21 - k11 * k20) * id, i21 = (k01 * k20 - k00 * k21) * id, i22 = (k00 * k11 - k01 * k10) * id;

    float dvx = gw[ray] + 0.5f, dvy = gh[ray] + 0.5f;
    float cx = dvx * i00 + dvy * i01 + i02;
    float cy = dvx * i10 + dvy * i11 + i12;
    float cz = dvx * i20 + dvy * i21 + i22;

    const float* Er = gE + (size_t)ray * 16;
    float ox = Er[3], oy = Er[7], oz = Er[11];
    float rdx = Er[0] * cx + Er[1] * cy + Er[2]  * cz;
    float rdy = Er[4] * cx + Er[5] * cy + Er[6]  * cz;
    float rdz = Er[8] * cx + Er[9] * cy + Er[10] * cz;
    float rn  = sqrtf(rdx * rdx + rdy * rdy + rdz * rdz);
    float irn = __fdividef(1.0f, rn);
    float ndx = rdx * irn, ndy = rdy * irn, ndz = rdz * irn;

    const float bd2v = gbd2[0];

    // per-ray layer1 init: bc1[j] + dir terms (rows 32..34 of Wc1); lane j
    {
        int j = lane;
        float ini = gbc1[j];
        ini = fmaf(ndx, gWc1[1024 + j], ini);
        ini = fmaf(ndy, gWc1[1056 + j], ini);
        ini = fmaf(ndz, gWc1[1088 + j], ini);
        sInit[warp][j] = ini;
    }
    __syncwarp();

    // ---- coarse pass: 6 samples/lane, single pass over density weights ----
    float alpha[6];
    {
        float cpx[6], cpy[6], cpz[6];
#pragma unroll
        for (int q = 0; q < 6; ++q) {
            float zq = sZc[lane * 6 + q];
            cpx[q] = fmaf(rdx, zq, ox);
            cpy[q] = fmaf(rdy, zq, oy);
            cpz[q] = fmaf(rdz, zq, oz);
            mip_scale(cpx[q], cpy[q], cpz[q]);
        }
        float sg[6] = { bd2v, bd2v, bd2v, bd2v, bd2v, bd2v };
#pragma unroll 4
        for (int c = 0; c < 32; ++c) {
            float4 wd = sWd1p[c];
            float v2 = sWd2[c];
#pragma unroll
            for (int q = 0; q < 6; ++q) {
                float t = fmaf(cpx[q], wd.x, fmaf(cpy[q], wd.y, fmaf(cpz[q], wd.z, wd.w)));
                t = fmaxf(t, 0.0f);
                sg[q] = fmaf(t, v2, sg[q]);
            }
        }
#pragma unroll
        for (int q = 0; q < 6; ++q) {
            int s = lane * 6 + q;
            float d = (s < 128) ? 0.0078125f : ((s < 191) ? 0.015625f : 0.0f);
            alpha[q] = 1.0f - fexp(-fsoftplus(sg[q]) * d);
        }
    }

    // ---- transmittance weights (warp multiplicative scan) ----
    float om[6]; float lprod = 1.0f;
#pragma unroll
    for (int q = 0; q < 6; ++q) { om[q] = 1.0f - alpha[q]; lprod *= om[q]; }
    float scanp = lprod;
#pragma unroll
    for (int o = 1; o < 32; o <<= 1) {
        float t = __shfl_up_sync(0xffffffffu, scanp, o);
        if (lane >= o) scanp *= t;
    }
    float T = __shfl_up_sync(0xffffffffu, scanp, 1);
    if (lane == 0) T = 1.0f;
    float wgt[6];
#pragma unroll
    for (int q = 0; q < 6; ++q) { wgt[q] = alpha[q] * T; T *= om[q]; }

    // ---- reweight ----
    float wprev = __shfl_up_sync(0xffffffffu, wgt[5], 1);   if (lane == 0)  wprev = 0.0f;
    float wnext = __shfl_down_sync(0xffffffffu, wgt[0], 1); if (lane == 31) wnext = 0.0f;
    float wr[6]; float lsum = 0.0f;
#pragma unroll
    for (int q = 0; q < 6; ++q) {
        float wm = (q == 0) ? wprev : wgt[q - 1];
        float wp = (q == 5) ? wnext : wgt[q + 1];
        float v = 0.5f * (fmaxf(wm, wgt[q]) + fmaxf(wgt[q], wp)) + (float)(0.02 / 192.0);
        int s = lane * 6 + q;
        v *= (s < 128) ? (float)(128.0 / 192.0) : (float)(64.0 / 192.0);
        wr[q] = v; lsum += v;
    }
    float tot = lsum;
#pragma unroll
    for (int o = 16; o; o >>= 1) tot += __shfl_xor_sync(0xffffffffu, tot, o);
    float itot = __fdividef(1.0f, tot);

    float wn[6]; float ls2 = 0.0f;
#pragma unroll
    for (int q = 0; q < 6; ++q) { wn[q] = wr[q] * itot; ls2 += wn[q]; }
    float scs = ls2;
#pragma unroll
    for (int o = 1; o < 32; o <<= 1) {
        float t = __shfl_up_sync(0xffffffffu, scs, o);
        if (lane >= o) scs += t;
    }
    float base = __shfl_up_sync(0xffffffffu, scs, 1);
    if (lane == 0) base = 0.0f;
    float run = base;
#pragma unroll
    for (int q = 0; q < 6; ++q) { run += wn[q]; sCdf[warp][lane * 6 + q] = run; }
    sCdf[warp][192 + lane] = 1e30f;
    sCdf[warp][224 + lane] = 1e30f;
    __syncwarp();

    const float cdfl = sCdf[warp][1];
    const float cdfh = sCdf[warp][190];

    // ---- importance sampling: unconditional branchless bit-ladder ----
    float zlf[4];
#pragma unroll
    for (int q = 0; q < 4; ++q) {
        int j = (lane << 2) + q;
        float r = tf_uniform((unsigned)(ray * NFINE + j));
        float u = (float)j * 0.0078125f + r * 0.0078125f;
        u = u * (cdfh - cdfl) + cdfl;
        int k = 0;
#pragma unroll
        for (int s = 128; s >= 1; s >>= 1) {
            int cand = k + s;
            if (sCdf[warp][cand] <= u) k = cand;
        }
        float cb = sCdf[warp][k], ca = sCdf[warp][k + 1];
        float tt = __fdividef(u - cb, ca - cb);
        float zb = zmid_c(k), za = zmid_c(k + 1);
        zlf[q] = zb + (za - zb) * tt;
    }

    // ---- fine pass: per q-tile (samples s = 4*lane + q), HMMA GEMM ----
    const float bc2x = gbc2[0], bc2y = gbc2[1], bc2z = gbc2[2];
    float* aT = sT[warp];
    float sig[4], rr[4], rg[4], rb[4];

    // q-invariant init pairs (cols 8nt+2tig, +1)
    float2 iniv[4];
#pragma unroll
    for (int nt = 0; nt < 4; ++nt)
        iniv[nt] = *(const float2*)&sInit[warp][8 * nt + 2 * tig];

    const int xsrc = 4 * (lane & 7);   // shfl source lane for exchange
    const int ssel = lane >> 3;        // which part[] the owner needs

#pragma unroll
    for (int q = 0; q < 4; ++q) {
        // 1) compute hidden t for own sample; stage tf32 T tile; sigma path fp32
        float zq = fexp10(zlf[q]);
        float pxq = fmaf(rdx, zq, ox), pyq = fmaf(rdy, zq, oy), pzq = fmaf(rdz, zq, oz);
        mip_scale(pxq, pyq, pzq);
        float sgq = bd2v;
#pragma unroll
        for (int cg = 0; cg < 8; ++cg) {
            uint4 tc;
#pragma unroll
            for (int cc = 0; cc < 4; ++cc) {
                int c = 4 * cg + cc;
                float4 wd = sWd1p[c];
                float t = fmaf(pxq, wd.x, fmaf(pyq, wd.y, fmaf(pzq, wd.z, wd.w)));
                t = fmaxf(t, 0.0f);
                sgq = fmaf(t, sWd2[c], sgq);
                ((uint32_t*)&tc)[cc] = f2tf32(t);
            }
            *(uint4*)(aT + lane * 32 + 4 * (cg ^ (lane & 7))) = tc;
        }
        sig[q] = fsoftplus(sgq);
        __syncwarp();   // sole sync: t tile visible to all lanes

        // 2) GEMM, kt-outer with both m-tiles live
        float d[32];                 // [mt][nt][4]
#pragma unroll
        for (int mt = 0; mt < 2; ++mt)
#pragma unroll
            for (int nt = 0; nt < 4; ++nt) {
                d[16 * mt + 4 * nt + 0] = iniv[nt].x;
                d[16 * mt + 4 * nt + 1] = iniv[nt].y;
                d[16 * mt + 4 * nt + 2] = iniv[nt].x;
                d[16 * mt + 4 * nt + 3] = iniv[nt].y;
            }
        const int sw = 4 * gid;
#pragma unroll
        for (int kt = 0; kt < 4; ++kt) {
            int c0 = (8 * kt + tig) ^ sw;
            int c1 = (8 * kt + tig + 4) ^ sw;
            uint32_t a0 = *(const uint32_t*)(aT + gid * 32 + c0);
            uint32_t a1 = *(const uint32_t*)(aT + (gid + 8) * 32 + c0);
            uint32_t a2 = *(const uint32_t*)(aT + gid * 32 + c1);
            uint32_t a3 = *(const uint32_t*)(aT + (gid + 8) * 32 + c1);
            uint32_t a4 = *(const uint32_t*)(aT + (gid + 16) * 32 + c0);
            uint32_t a5 = *(const uint32_t*)(aT + (gid + 24) * 32 + c0);
            uint32_t a6 = *(const uint32_t*)(aT + (gid + 16) * 32 + c1);
            uint32_t a7 = *(const uint32_t*)(aT + (gid + 24) * 32 + c1);
#pragma unroll
            for (int nt = 0; nt < 4; ++nt) {
                uint2 bp = sBfrag[kt][nt][lane];
                mma_tf32(d + 4 * nt,      a0, a1, a2, a3, bp.x, bp.y);
                mma_tf32(d + 16 + 4 * nt, a4, a5, a6, a7, bp.x, bp.y);
            }
        }

        // 3) d-frag epilogue: relu + Wc2 partial dot (cols 8nt+2tig, +1)
        float part[4][3];
#pragma unroll
        for (int s = 0; s < 4; ++s) { part[s][0] = 0.0f; part[s][1] = 0.0f; part[s][2] = 0.0f; }
#pragma unroll
        for (int mt = 0; mt < 2; ++mt)
#pragma unroll
            for (int nt = 0; nt < 4; ++nt) {
                float h00 = fmaxf(d[16 * mt + 4 * nt + 0], 0.0f);
                float h01 = fmaxf(d[16 * mt + 4 * nt + 1], 0.0f);
                float h10 = fmaxf(d[16 * mt + 4 * nt + 2], 0.0f);
                float h11 = fmaxf(d[16 * mt + 4 * nt + 3], 0.0f);
                int jj = 8 * nt + 2 * tig;
#pragma unroll
                for (int c = 0; c < 3; ++c) {
                    float2 u2 = *(const float2*)&sWc2c[c][jj];
                    part[2 * mt + 0][c] = fmaf(h00, u2.x, fmaf(h01, u2.y, part[2 * mt + 0][c]));
                    part[2 * mt + 1][c] = fmaf(h10, u2.x, fmaf(h11, u2.y, part[2 * mt + 1][c]));
                }
            }

        // 4) tig-group butterfly: full sums land in ALL lanes of each group
#pragma unroll
        for (int s = 0; s < 4; ++s)
#pragma unroll
            for (int c = 0; c < 3; ++c) {
                part[s][c] += __shfl_xor_sync(0xffffffffu, part[s][c], 1);
                part[s][c] += __shfl_xor_sync(0xffffffffu, part[s][c], 2);
            }

        // 5) exchange via shfl: owner lane r pulls part[r>>3] from group r&7
        float acc[3];
#pragma unroll
        for (int c = 0; c < 3; ++c) {
            float v0 = __shfl_sync(0xffffffffu, part[0][c], xsrc);
            float v1 = __shfl_sync(0xffffffffu, part[1][c], xsrc);
            float v2 = __shfl_sync(0xffffffffu, part[2][c], xsrc);
            float v3 = __shfl_sync(0xffffffffu, part[3][c], xsrc);
            float lo = (ssel & 1) ? v1 : v0;
            float hi = (ssel & 1) ? v3 : v2;
            acc[c] = (ssel & 2) ? hi : lo;
        }
        rr[q] = fsigmoid(acc[0] + bc2x);
        rg[q] = fsigmoid(acc[1] + bc2y);
        rb[q] = fsigmoid(acc[2] + bc2z);
    }

    // ---- fine weights + accumulation ----
    float znx = __shfl_down_sync(0xffffffffu, zlf[0], 1);
    float dl[4];
    dl[0] = zlf[1] - zlf[0];
    dl[1] = zlf[2] - zlf[1];
    dl[2] = zlf[3] - zlf[2];
    dl[3] = (lane == 31) ? 0.0f : (znx - zlf[3]);

    float al[4], om2[4]; float lp = 1.0f;
#pragma unroll
    for (int q = 0; q < 4; ++q) {
        al[q] = 1.0f - fexp(-sig[q] * dl[q]);
        om2[q] = 1.0f - al[q];
        lp *= om2[q];
    }
    float scan2 = lp;
#pragma unroll
    for (int o = 1; o < 32; o <<= 1) {
        float t = __shfl_up_sync(0xffffffffu, scan2, o);
        if (lane >= o) scan2 *= t;
    }
    float T2 = __shfl_up_sync(0xffffffffu, scan2, 1);
    if (lane == 0) T2 = 1.0f;
    float w4[4];
#pragma unroll
    for (int q = 0; q < 4; ++q) { w4[q] = al[q] * T2; T2 *= om2[q]; }

    float ir = 0.0f, ig = 0.0f, ib = 0.0f, ivd = 0.0f, ws = 0.0f;
#pragma unroll
    for (int q = 0; q < 4; ++q) {
        ir = fmaf(w4[q], rr[q], ir);
        ig = fmaf(w4[q], rg[q], ig);
        ib = fmaf(w4[q], rb[q], ib);
        ivd = fmaf(w4[q], fexp10(-zlf[q]), ivd);
        ws  += w4[q];
    }
#pragma unroll
    for (int o = 16; o; o >>= 1) {
        ir  += __shfl_xor_sync(0xffffffffu, ir, o);
        ig  += __shfl_xor_sync(0xffffffffu, ig, o);
        ib  += __shfl_xor_sync(0xffffffffu, ib, o);
        ivd += __shfl_xor_sync(0xffffffffu, ivd, o);
        ws  += __shfl_xor_sync(0xffffffffu, ws, o);
    }

    // ---- stores ----
    *(float4*)(oW + (size_t)ray * NFINE + lane * 4) =
        make_float4(w4[0], w4[1], w4[2], w4[3]);
    *(float4*)(oZ + (size_t)ray * NFINE + lane * 4) =
        make_float4((zlf[0] + 1.0f) * 0.5f, (zlf[1] + 1.0f) * 0.5f,
                    (zlf[2] + 1.0f) * 0.5f, (zlf[3] + 1.0f) * 0.5f);

    if (lane == 0) {
        float oneMw = 1.0f - ws;
        oImg[ray * 3 + 0] = ir + oneMw * gbg[0];
        oImg[ray * 3 + 1] = ig + oneMw * gbg[1];
        oImg[ray * 3 + 2] = ib + oneMw * gbg[2];
        oInv[ray] = ivd;
    }
}

extern "C" void kernel_launch(void* const* d_in, const int* in_sizes, int n_in,
                              void* d_out, int out_size) {
    const float* h   = (const float*)d_in[1];
    const float* w   = (const float*)d_in[2];
    const float* K   = (const float*)d_in[3];
    const float* E   = (const float*)d_in[4];
    const float* bg  = (const float*)d_in[5];
    const float* Wd1 = (const float*)d_in[6];
    const float* bd1 = (const float*)d_in[7];
    const float* Wd2 = (const float*)d_in[8];
    const float* bd2 = (const float*)d_in[9];
    const float* Wc1 = (const float*)d_in[10];
    const float* bc1 = (const float*)d_in[11];
    const float* Wc2 = (const float*)d_in[12];
    const float* bc2 = (const float*)d_in[13];

    float* out   = (float*)d_out;
    float* oImg  = out;
    float* oW    = out + NRAYS * 3;
    float* oZ    = oW + (size_t)NRAYS * NFINE;
    float* oInv  = oZ + (size_t)NRAYS * NFINE;

    nerf_fused<<<NRAYS / 4, 128>>>(h, w, K, E, bg,
                                   Wd1, bd1, Wd2, bd2,
                                   Wc1, bc1, Wc2, bc2,
                                   oImg, oW, oZ, oInv);
}

// round 14
// speedup vs baseline: 1.0217x; 1.0217x over previous
#include <cuda_runtime.h>
#include <cstdint>

#define NRAYS 16384
#define NFINE 128

typedef unsigned long long u64;

// ---- fast transcendentals ----
__device__ __forceinline__ float fexp(float x)   { return __expf(x); }
__device__ __forceinline__ float fexp10(float x) { return __exp10f(x); }
__device__ __forceinline__ float frsqrt_approx(float x) {
    float r; asm("rsqrt.approx.f32 %0, %1;" : "=f"(r) : "f"(x)); return r;
}
__device__ __forceinline__ float fsigmoid(float x) {
    return __fdividef(1.0f, 1.0f + __expf(-x));
}
__device__ __forceinline__ float fsoftplus(float x) {
    return fmaxf(x, 0.0f) + __logf(1.0f + __expf(-fabsf(x)));
}
__device__ __forceinline__ uint32_t f2tf32(float x) {
    uint32_t r; asm("cvt.rna.tf32.f32 %0, %1;" : "=r"(r) : "f"(x)); return r;
}
// m16n8k8 tf32 HMMA (standard PTX, sm_80+; runs on sm_103 tensor pipe)
__device__ __forceinline__ void mma_tf32(float* d,
    uint32_t a0, uint32_t a1, uint32_t a2, uint32_t a3,
    uint32_t b0, uint32_t b1)
{
    asm volatile(
        "mma.sync.aligned.m16n8k8.row.col.f32.tf32.tf32.f32 "
        "{%0,%1,%2,%3}, {%4,%5,%6,%7}, {%8,%9}, {%0,%1,%2,%3};"
        : "+f"(d[0]), "+f"(d[1]), "+f"(d[2]), "+f"(d[3])
        : "r"(a0), "r"(a1), "r"(a2), "r"(a3), "r"(b0), "r"(b1));
}

// exact z-grid helpers
__device__ __forceinline__ float zlog_c(int i) {
    return (i < 128) ? (float)(i - 128) * 0.0078125f : (float)(i - 128) * 0.015625f;
}
__device__ __forceinline__ float zmid_c(int i) {
    return 0.5f * (zlog_c(i) + zlog_c(i + 1));
}
__device__ __forceinline__ unsigned rotl32(unsigned x, int r) {
    return __funnelshift_l(x, x, r);
}

// JAX threefry2x32, key=(0,42), partitionable counter mode: bits = out0^out1
__device__ __forceinline__ float tf_uniform(unsigned idx) {
    unsigned x0 = 0u, x1 = idx;
    const unsigned ks1 = 42u;
    const unsigned ks2 = 42u ^ 0x1BD11BDAu;
    x0 += 0u; x1 += ks1;
#define TF_RND(R) { x0 += x1; x1 = rotl32(x1, R); x1 ^= x0; }
    TF_RND(13) TF_RND(15) TF_RND(26) TF_RND(6)
    x0 += ks1; x1 += ks2 + 1u;
    TF_RND(17) TF_RND(29) TF_RND(16) TF_RND(24)
    x0 += ks2; x1 += 0u + 2u;
    TF_RND(13) TF_RND(15) TF_RND(26) TF_RND(6)
    x0 += 0u; x1 += ks1 + 3u;
    TF_RND(17) TF_RND(29) TF_RND(16) TF_RND(24)
    x0 += ks1; x1 += ks2 + 4u;
    TF_RND(13) TF_RND(15) TF_RND(26) TF_RND(6)
    x0 += ks2; x1 += 0u + 5u;
#undef TF_RND
    unsigned bits = x0 ^ x1;
    return __uint_as_float((bits >> 9) | 0x3f800000u) - 1.0f;
}

__device__ __forceinline__ void mip_scale(float& x, float& y, float& z) {
    float d2 = x * x + y * y + z * z;
    float r  = frsqrt_approx(d2);
    float d  = d2 * r;
    if (d > 1.0f) {
        float s = (2.0f - r) * r;
        x *= s; y *= s; z *= s;
    }
}

__global__ void __launch_bounds__(128, 4) nerf_fused(
    const float* __restrict__ gh, const float* __restrict__ gw,
    const float* __restrict__ gK, const float* __restrict__ gE,
    const float* __restrict__ gbg,
    const float* __restrict__ gWd1, const float* __restrict__ gbd1,
    const float* __restrict__ gWd2, const float* __restrict__ gbd2,
    const float* __restrict__ gWc1, const float* __restrict__ gbc1,
    const float* __restrict__ gWc2, const float* __restrict__ gbc2,
    float* __restrict__ oImg, float* __restrict__ oW,
    float* __restrict__ oZ, float* __restrict__ oInv)
{
    __shared__ float4 sWd1p[32];            // (w0,w1,w2,b) per hidden c
    __shared__ float  sWd2[32];
    __shared__ __align__(16) float sWc2c[3][32];
    __shared__ float  sInit[4][32];         // per-ray bc1 + dir terms
    __shared__ uint2  sBfrag[4][4][32];     // b-frags [kt][nt][lane] = (b0,b1) tf32
    __shared__ float  sCdf[4][256];
    __shared__ float  sZc[192];             // exp10(zlog_c(i)) — ray-invariant
    __shared__ __align__(16) float sT[4][2][1024];   // double-buffered T tile
    __shared__ __align__(16) float4 sEx[4][2][32];   // double-buffered rgb exchange

    const int tid  = threadIdx.x;
    const int lane = tid & 31;
    const int warp = tid >> 5;
    const int gid  = lane >> 2;
    const int tig  = lane & 3;
    const int ray  = (blockIdx.x << 2) + warp;

    // ---- stage weights + B fragments + z-table ----
    if (tid < 32) {
        sWd1p[tid] = make_float4(gWd1[tid], gWd1[32 + tid], gWd1[64 + tid], gbd1[tid]);
        sWd2[tid]  = gWd2[tid];
        sWc2c[0][tid] = gWc2[tid * 3 + 0];
        sWc2c[1][tid] = gWc2[tid * 3 + 1];
        sWc2c[2][tid] = gWc2[tid * 3 + 2];
    }
    for (int i = tid; i < 512; i += 128) {
        int kt = i >> 7, nt = (i >> 5) & 3, l = i & 31;
        int lt = l & 3, lg = l >> 2;
        int c0 = 8 * kt + lt, j = 8 * nt + lg;
        sBfrag[kt][nt][l] = make_uint2(f2tf32(gWc1[c0 * 32 + j]),
                                       f2tf32(gWc1[(c0 + 4) * 32 + j]));
    }
    for (int i = tid; i < 192; i += 128) sZc[i] = fexp10(zlog_c(i));
    __syncthreads();

    // ---- ray setup ----
    float k00 = gK[0], k01 = gK[1], k02 = gK[2];
    float k10 = gK[3], k11 = gK[4], k12 = gK[5];
    float k20 = gK[6], k21 = gK[7], k22 = gK[8];
    float det = k00 * (k11 * k22 - k12 * k21)
              + k01 * (k12 * k20 - k10 * k22)
              + k02 * (k10 * k21 - k11 * k20);
    float id = 1.0f / det;
    float i00 = (k11 * k22 - k12 * k21) * id, i01 = (k02 * k21 - k01 * k22) * id, i02 = (k01 * k12 - k02 * k11) * id;
    float i10 = (k12 * k20 - k10 * k22) * id, i11 = (k00 * k22 - k02 * k20) * id, i12 = (k02 * k10 - k00 * k12) * id;
    float i20 = (k10 * k21 - k11 * k20) * id, i21 = (k01 * k20 - k00 * k21) * id, i22 = (k00 * k11 - k01 * k10) * id;

    float dvx = gw[ray] + 0.5f, dvy = gh[ray] + 0.5f;
    float cx = dvx * i00 + dvy * i01 + i02;
    float cy = dvx * i10 + dvy * i11 + i12;
    float cz = dvx * i20 + dvy * i21 + i22;

    const float* Er = gE + (size_t)ray * 16;
    float ox = Er[3], oy = Er[7], oz = Er[11];
    float rdx = Er[0] * cx + Er[1] * cy + Er[2]  * cz;
    float rdy = Er[4] * cx + Er[5] * cy + Er[6]  * cz;
    float rdz = Er[8] * cx + Er[9] * cy + Er[10] * cz;
    float rn  = sqrtf(rdx * rdx + rdy * rdy + rdz * rdz);
    float irn = __fdividef(1.0f, rn);
    float ndx = rdx * irn, ndy = rdy * irn, ndz = rdz * irn;

    const float bd2v = gbd2[0];

    // per-ray layer1 init: bc1[j] + dir terms (rows 32..34 of Wc1); lane j
    {
        int j = lane;
        float ini = gbc1[j];
        ini = fmaf(ndx, gWc1[1024 + j], ini);
        ini = fmaf(ndy, gWc1[1056 + j], ini);
        ini = fmaf(ndz, gWc1[1088 + j], ini);
        sInit[warp][j] = ini;
    }
    __syncwarp();

    // ---- coarse pass: 6 samples/lane, single pass over density weights ----
    float alpha[6];
    {
        float cpx[6], cpy[6], cpz[6];
#pragma unroll
        for (int q = 0; q < 6; ++q) {
            float zq = sZc[lane * 6 + q];
            cpx[q] = fmaf(rdx, zq, ox);
            cpy[q] = fmaf(rdy, zq, oy);
            cpz[q] = fmaf(rdz, zq, oz);
            mip_scale(cpx[q], cpy[q], cpz[q]);
        }
        float sg[6] = { bd2v, bd2v, bd2v, bd2v, bd2v, bd2v };
#pragma unroll 4
        for (int c = 0; c < 32; ++c) {
            float4 wd = sWd1p[c];
            float v2 = sWd2[c];
#pragma unroll
            for (int q = 0; q < 6; ++q) {
                float t = fmaf(cpx[q], wd.x, fmaf(cpy[q], wd.y, fmaf(cpz[q], wd.z, wd.w)));
                t = fmaxf(t, 0.0f);
                sg[q] = fmaf(t, v2, sg[q]);
            }
        }
#pragma unroll
        for (int q = 0; q < 6; ++q) {
            int s = lane * 6 + q;
            float d = (s < 128) ? 0.0078125f : ((s < 191) ? 0.015625f : 0.0f);
            alpha[q] = 1.0f - fexp(-fsoftplus(sg[q]) * d);
        }
    }

    // ---- transmittance weights (warp multiplicative scan) ----
    float om[6]; float lprod = 1.0f;
#pragma unroll
    for (int q = 0; q < 6; ++q) { om[q] = 1.0f - alpha[q]; lprod *= om[q]; }
    float scanp = lprod;
#pragma unroll
    for (int o = 1; o < 32; o <<= 1) {
        float t = __shfl_up_sync(0xffffffffu, scanp, o);
        if (lane >= o) scanp *= t;
    }
    float T = __shfl_up_sync(0xffffffffu, scanp, 1);
    if (lane == 0) T = 1.0f;
    float wgt[6];
#pragma unroll
    for (int q = 0; q < 6; ++q) { wgt[q] = alpha[q] * T; T *= om[q]; }

    // ---- reweight ----
    float wprev = __shfl_up_sync(0xffffffffu, wgt[5], 1);   if (lane == 0)  wprev = 0.0f;
    float wnext = __shfl_down_sync(0xffffffffu, wgt[0], 1); if (lane == 31) wnext = 0.0f;
    float wr[6]; float lsum = 0.0f;
#pragma unroll
    for (int q = 0; q < 6; ++q) {
        float wm = (q == 0) ? wprev : wgt[q - 1];
        float wp = (q == 5) ? wnext : wgt[q + 1];
        float v = 0.5f * (fmaxf(wm, wgt[q]) + fmaxf(wgt[q], wp)) + (float)(0.02 / 192.0);
        int s = lane * 6 + q;
        v *= (s < 128) ? (float)(128.0 / 192.0) : (float)(64.0 / 192.0);
        wr[q] = v; lsum += v;
    }
    float tot = lsum;
#pragma unroll
    for (int o = 16; o; o >>= 1) tot += __shfl_xor_sync(0xffffffffu, tot, o);
    float itot = __fdividef(1.0f, tot);

    float wn[6]; float ls2 = 0.0f;
#pragma unroll
    for (int q = 0; q < 6; ++q) { wn[q] = wr[q] * itot; ls2 += wn[q]; }
    float scs = ls2;
#pragma unroll
    for (int o = 1; o < 32; o <<= 1) {
        float t = __shfl_up_sync(0xffffffffu, scs, o);
        if (lane >= o) scs += t;
    }
    float base = __shfl_up_sync(0xffffffffu, scs, 1);
    if (lane == 0) base = 0.0f;
    float run = base;
#pragma unroll
    for (int q = 0; q < 6; ++q) { run += wn[q]; sCdf[warp][lane * 6 + q] = run; }
    sCdf[warp][192 + lane] = 1e30f;
    sCdf[warp][224 + lane] = 1e30f;
    __syncwarp();

    const float cdfl = sCdf[warp][1];
    const float cdfh = sCdf[warp][190];

    // ---- importance sampling: unconditional branchless bit-ladder ----
    float zlf[4];
#pragma unroll
    for (int q = 0; q < 4; ++q) {
        int j = (lane << 2) + q;
        float r = tf_uniform((unsigned)(ray * NFINE + j));
        float u = (float)j * 0.0078125f + r * 0.0078125f;
        u = u * (cdfh - cdfl) + cdfl;
        int k = 0;
#pragma unroll
        for (int s = 128; s >= 1; s >>= 1) {
            int cand = k + s;
            if (sCdf[warp][cand] <= u) k = cand;
        }
        float cb = sCdf[warp][k], ca = sCdf[warp][k + 1];
        float tt = __fdividef(u - cb, ca - cb);
        float zb = zmid_c(k), za = zmid_c(k + 1);
        zlf[q] = zb + (za - zb) * tt;
    }

    // ---- fine pass: per q-tile (samples s = 4*lane + q), HMMA GEMM ----
    const float bc2x = gbc2[0], bc2y = gbc2[1], bc2z = gbc2[2];
    float sig[4], rr[4], rg[4], rb[4];

    // q-invariant init pairs (cols 8nt+2tig, +1)
    float2 iniv[4];
#pragma unroll
    for (int nt = 0; nt < 4; ++nt)
        iniv[nt] = *(const float2*)&sInit[warp][8 * nt + 2 * tig];

#pragma unroll
    for (int q = 0; q < 4; ++q) {
        const int pb = q & 1;               // buffer parity
        float* aT = sT[warp][pb];

        // 1) compute hidden t for own sample; stage tf32 T tile; sigma path fp32
        float zq = fexp10(zlf[q]);
        float pxq = fmaf(rdx, zq, ox), pyq = fmaf(rdy, zq, oy), pzq = fmaf(rdz, zq, oz);
        mip_scale(pxq, pyq, pzq);
        float sgq = bd2v;
#pragma unroll
        for (int cg = 0; cg < 8; ++cg) {
            uint4 tc;
#pragma unroll
            for (int cc = 0; cc < 4; ++cc) {
                int c = 4 * cg + cc;
                float4 wd = sWd1p[c];
                float t = fmaf(pxq, wd.x, fmaf(pyq, wd.y, fmaf(pzq, wd.z, wd.w)));
                t = fmaxf(t, 0.0f);
                sgq = fmaf(t, sWd2[c], sgq);
                ((uint32_t*)&tc)[cc] = f2tf32(t);
            }
            *(uint4*)(aT + lane * 32 + 4 * (cg ^ (lane & 7))) = tc;
        }
        sig[q] = fsoftplus(sgq);
        __syncwarp();                        // RAW: T tile

        // 2) GEMM, kt-outer with both m-tiles live
        float d[32];                 // [mt][nt][4]
#pragma unroll
        for (int mt = 0; mt < 2; ++mt)
#pragma unroll
            for (int nt = 0; nt < 4; ++nt) {
                d[16 * mt + 4 * nt + 0] = iniv[nt].x;
                d[16 * mt + 4 * nt + 1] = iniv[nt].y;
                d[16 * mt + 4 * nt + 2] = iniv[nt].x;
                d[16 * mt + 4 * nt + 3] = iniv[nt].y;
            }
        const int sw = 4 * gid;
#pragma unroll
        for (int kt = 0; kt < 4; ++kt) {
            int c0 = (8 * kt + tig) ^ sw;
            int c1 = (8 * kt + tig + 4) ^ sw;
            uint32_t a0 = *(const uint32_t*)(aT + gid * 32 + c0);
            uint32_t a1 = *(const uint32_t*)(aT + (gid + 8) * 32 + c0);
            uint32_t a2 = *(const uint32_t*)(aT + gid * 32 + c1);
            uint32_t a3 = *(const uint32_t*)(aT + (gid + 8) * 32 + c1);
            uint32_t a4 = *(const uint32_t*)(aT + (gid + 16) * 32 + c0);
            uint32_t a5 = *(const uint32_t*)(aT + (gid + 24) * 32 + c0);
            uint32_t a6 = *(const uint32_t*)(aT + (gid + 16) * 32 + c1);
            uint32_t a7 = *(const uint32_t*)(aT + (gid + 24) * 32 + c1);
#pragma unroll
            for (int nt = 0; nt < 4; ++nt) {
                uint2 bp = sBfrag[kt][nt][lane];
                mma_tf32(d + 4 * nt,      a0, a1, a2, a3, bp.x, bp.y);
                mma_tf32(d + 16 + 4 * nt, a4, a5, a6, a7, bp.x, bp.y);
            }
        }

        // 3) d-frag epilogue: relu + Wc2 partial dot (cols 8nt+2tig, +1)
        float part[4][3];
#pragma unroll
        for (int s = 0; s < 4; ++s) { part[s][0] = 0.0f; part[s][1] = 0.0f; part[s][2] = 0.0f; }
#pragma unroll
        for (int mt = 0; mt < 2; ++mt)
#pragma unroll
            for (int nt = 0; nt < 4; ++nt) {
                float h00 = fmaxf(d[16 * mt + 4 * nt + 0], 0.0f);
                float h01 = fmaxf(d[16 * mt + 4 * nt + 1], 0.0f);
                float h10 = fmaxf(d[16 * mt + 4 * nt + 2], 0.0f);
                float h11 = fmaxf(d[16 * mt + 4 * nt + 3], 0.0f);
                int jj = 8 * nt + 2 * tig;
#pragma unroll
                for (int c = 0; c < 3; ++c) {
                    float2 u2 = *(const float2*)&sWc2c[c][jj];
                    part[2 * mt + 0][c] = fmaf(h00, u2.x, fmaf(h01, u2.y, part[2 * mt + 0][c]));
                    part[2 * mt + 1][c] = fmaf(h10, u2.x, fmaf(h11, u2.y, part[2 * mt + 1][c]));
                }
            }

        // 4) tig-group butterfly reduction
#pragma unroll
        for (int s = 0; s < 4; ++s)
#pragma unroll
            for (int c = 0; c < 3; ++c) {
                part[s][c] += __shfl_xor_sync(0xffffffffu, part[s][c], 1);
                part[s][c] += __shfl_xor_sync(0xffffffffu, part[s][c], 2);
            }

        // 5) exchange to sample-owner lane via dedicated parity buffer
        float4* exch = &sEx[warp][pb][0];
        if (tig == 0) {
#pragma unroll
            for (int s = 0; s < 4; ++s) {
                int row = 16 * (s >> 1) + 8 * (s & 1) + gid;
                exch[row] = make_float4(part[s][0], part[s][1], part[s][2], 0.0f);
            }
        }
        __syncwarp();                        // RAW: exchange buffer
        float4 v = exch[lane];
        rr[q] = fsigmoid(v.x + bc2x);
        rg[q] = fsigmoid(v.y + bc2y);
        rb[q] = fsigmoid(v.z + bc2z);
        // no trailing sync: next q uses the other parity buffers
    }

    // ---- fine weights + accumulation ----
    float znx = __shfl_down_sync(0xffffffffu, zlf[0], 1);
    float dl[4];
    dl[0] = zlf[1] - zlf[0];
    dl[1] = zlf[2] - zlf[1];
    dl[2] = zlf[3] - zlf[2];
    dl[3] = (lane == 31) ? 0.0f : (znx - zlf[3]);

    float al[4], om2[4]; float lp = 1.0f;
#pragma unroll
    for (int q = 0; q < 4; ++q) {
        al[q] = 1.0f - fexp(-sig[q] * dl[q]);
        om2[q] = 1.0f - al[q];
        lp *= om2[q];
    }
    float scan2 = lp;
#pragma unroll
    for (int o = 1; o < 32; o <<= 1) {
        float t = __shfl_up_sync(0xffffffffu, scan2, o);
        if (lane >= o) scan2 *= t;
    }
    float T2 = __shfl_up_sync(0xffffffffu, scan2, 1);
    if (lane == 0) T2 = 1.0f;
    float w4[4];
#pragma unroll
    for (int q = 0; q < 4; ++q) { w4[q] = al[q] * T2; T2 *= om2[q]; }

    float ir = 0.0f, ig = 0.0f, ib = 0.0f, ivd = 0.0f, ws = 0.0f;
#pragma unroll
    for (int q = 0; q < 4; ++q) {
        ir = fmaf(w4[q], rr[q], ir);
        ig = fmaf(w4[q], rg[q], ig);
        ib = fmaf(w4[q], rb[q], ib);
        ivd = fmaf(w4[q], fexp10(-zlf[q]), ivd);
        ws  += w4[q];
    }
#pragma unroll
    for (int o = 16; o; o >>= 1) {
        ir  += __shfl_xor_sync(0xffffffffu, ir, o);
        ig  += __shfl_xor_sync(0xffffffffu, ig, o);
        ib  += __shfl_xor_sync(0xffffffffu, ib, o);
        ivd += __shfl_xor_sync(0xffffffffu, ivd, o);
        ws  += __shfl_xor_sync(0xffffffffu, ws, o);
    }

    // ---- stores ----
    *(float4*)(oW + (size_t)ray * NFINE + lane * 4) =
        make_float4(w4[0], w4[1], w4[2], w4[3]);
    *(float4*)(oZ + (size_t)ray * NFINE + lane * 4) =
        make_float4((zlf[0] + 1.0f) * 0.5f, (zlf[1] + 1.0f) * 0.5f,
                    (zlf[2] + 1.0f) * 0.5f, (zlf[3] + 1.0f) * 0.5f);

    if (lane == 0) {
        float oneMw = 1.0f - ws;
        oImg[ray * 3 + 0] = ir + oneMw * gbg[0];
        oImg[ray * 3 + 1] = ig + oneMw * gbg[1];
        oImg[ray * 3 + 2] = ib + oneMw * gbg[2];
        oInv[ray] = ivd;
    }
}

extern "C" void kernel_launch(void* const* d_in, const int* in_sizes, int n_in,
                              void* d_out, int out_size) {
    const float* h   = (const float*)d_in[1];
    const float* w   = (const float*)d_in[2];
    const float* K   = (const float*)d_in[3];
    const float* E   = (const float*)d_in[4];
    const float* bg  = (const float*)d_in[5];
    const float* Wd1 = (const float*)d_in[6];
    const float* bd1 = (const float*)d_in[7];
    const float* Wd2 = (const float*)d_in[8];
    const float* bd2 = (const float*)d_in[9];
    const float* Wc1 = (const float*)d_in[10];
    const float* bc1 = (const float*)d_in[11];
    const float* Wc2 = (const float*)d_in[12];
    const float* bc2 = (const float*)d_in[13];

    float* out   = (float*)d_out;
    float* oImg  = out;
    float* oW    = out + NRAYS * 3;
    float* oZ    = oW + (size_t)NRAYS * NFINE;
    float* oInv  = oZ + (size_t)NRAYS * NFINE;

    nerf_fused<<<NRAYS / 4, 128>>>(h, w, K, E, bg,
                                   Wd1, bd1, Wd2, bd2,
                                   Wc1, bc1, Wc2, bc2,
                                   oImg, oW, oZ, oInv);
}

// round 15
// speedup vs baseline: 1.0258x; 1.0040x over previous
#include <cuda_runtime.h>
#include <cstdint>

#define NRAYS 16384
#define NFINE 128

typedef unsigned long long u64;

// ---- fast transcendentals ----
__device__ __forceinline__ float fexp(float x)   { return __expf(x); }
__device__ __forceinline__ float fexp10(float x) { return __exp10f(x); }
__device__ __forceinline__ float frsqrt_approx(float x) {
    float r; asm("rsqrt.approx.f32 %0, %1;" : "=f"(r) : "f"(x)); return r;
}
__device__ __forceinline__ float fsigmoid(float x) {
    return __fdividef(1.0f, 1.0f + __expf(-x));
}
__device__ __forceinline__ float fsoftplus(float x) {
    return fmaxf(x, 0.0f) + __logf(1.0f + __expf(-fabsf(x)));
}
__device__ __forceinline__ uint32_t f2tf32(float x) {
    uint32_t r; asm("cvt.rna.tf32.f32 %0, %1;" : "=r"(r) : "f"(x)); return r;
}
// m16n8k8 tf32 HMMA (standard PTX, sm_80+; runs on sm_103 tensor pipe)
__device__ __forceinline__ void mma_tf32(float* d,
    uint32_t a0, uint32_t a1, uint32_t a2, uint32_t a3,
    uint32_t b0, uint32_t b1)
{
    asm volatile(
        "mma.sync.aligned.m16n8k8.row.col.f32.tf32.tf32.f32 "
        "{%0,%1,%2,%3}, {%4,%5,%6,%7}, {%8,%9}, {%0,%1,%2,%3};"
        : "+f"(d[0]), "+f"(d[1]), "+f"(d[2]), "+f"(d[3])
        : "r"(a0), "r"(a1), "r"(a2), "r"(a3), "r"(b0), "r"(b1));
}

// exact z-grid helpers
__device__ __forceinline__ float zlog_c(int i) {
    return (i < 128) ? (float)(i - 128) * 0.0078125f : (float)(i - 128) * 0.015625f;
}
__device__ __forceinline__ float zmid_c(int i) {
    return 0.5f * (zlog_c(i) + zlog_c(i + 1));
}
__device__ __forceinline__ unsigned rotl32(unsigned x, int r) {
    return __funnelshift_l(x, x, r);
}

// JAX threefry2x32, key=(0,42), partitionable counter mode: bits = out0^out1
__device__ __forceinline__ float tf_uniform(unsigned idx) {
    unsigned x0 = 0u, x1 = idx;
    const unsigned ks1 = 42u;
    const unsigned ks2 = 42u ^ 0x1BD11BDAu;
    x0 += 0u; x1 += ks1;
#define TF_RND(R) { x0 += x1; x1 = rotl32(x1, R); x1 ^= x0; }
    TF_RND(13) TF_RND(15) TF_RND(26) TF_RND(6)
    x0 += ks1; x1 += ks2 + 1u;
    TF_RND(17) TF_RND(29) TF_RND(16) TF_RND(24)
    x0 += ks2; x1 += 0u + 2u;
    TF_RND(13) TF_RND(15) TF_RND(26) TF_RND(6)
    x0 += 0u; x1 += ks1 + 3u;
    TF_RND(17) TF_RND(29) TF_RND(16) TF_RND(24)
    x0 += ks1; x1 += ks2 + 4u;
    TF_RND(13) TF_RND(15) TF_RND(26) TF_RND(6)
    x0 += ks2; x1 += 0u + 5u;
#undef TF_RND
    unsigned bits = x0 ^ x1;
    return __uint_as_float((bits >> 9) | 0x3f800000u) - 1.0f;
}

__device__ __forceinline__ void mip_scale(float& x, float& y, float& z) {
    float d2 = x * x + y * y + z * z;
    float r  = frsqrt_approx(d2);
    float d  = d2 * r;
    if (d > 1.0f) {
        float s = (2.0f - r) * r;
        x *= s; y *= s; z *= s;
    }
}

__global__ void __launch_bounds__(128, 4) nerf_fused(
    const float* __restrict__ gh, const float* __restrict__ gw,
    const float* __restrict__ gK, const float* __restrict__ gE,
    const float* __restrict__ gbg,
    const float* __restrict__ gWd1, const float* __restrict__ gbd1,
    const float* __restrict__ gWd2, const float* __restrict__ gbd2,
    const float* __restrict__ gWc1, const float* __restrict__ gbc1,
    const float* __restrict__ gWc2, const float* __restrict__ gbc2,
    float* __restrict__ oImg, float* __restrict__ oW,
    float* __restrict__ oZ, float* __restrict__ oInv)
{
    __shared__ float4 sWd1p[32];            // (w0,w1,w2,b) per hidden c
    __shared__ float  sWd2[32];
    __shared__ __align__(16) float sWc2c[3][32];
    __shared__ float  sInit[4][32];         // per-ray bc1 + dir terms
    __shared__ uint2  sBfrag[4][4][32];     // b-frags [kt][nt][lane] = (b0,b1) tf32
    __shared__ float  sCdf[4][256];
    __shared__ float  sZc[192];             // exp10(zlog_c(i)) — ray-invariant
    __shared__ __align__(16) float sT[4][2][1024];   // double-buffered T tile
    __shared__ __align__(16) float4 sEx[4][2][32];   // double-buffered rgb exchange

    const int tid  = threadIdx.x;
    const int lane = tid & 31;
    const int warp = tid >> 5;
    const int gid  = lane >> 2;
    const int tig  = lane & 3;
    const int ray  = (blockIdx.x << 2) + warp;

    // ---- stage weights + B fragments + z-table ----
    if (tid < 32) {
        sWd1p[tid] = make_float4(gWd1[tid], gWd1[32 + tid], gWd1[64 + tid], gbd1[tid]);
        sWd2[tid]  = gWd2[tid];
        sWc2c[0][tid] = gWc2[tid * 3 + 0];
        sWc2c[1][tid] = gWc2[tid * 3 + 1];
        sWc2c[2][tid] = gWc2[tid * 3 + 2];
    }
    for (int i = tid; i < 512; i += 128) {
        int kt = i >> 7, nt = (i >> 5) & 3, l = i & 31;
        int lt = l & 3, lg = l >> 2;
        int c0 = 8 * kt + lt, j = 8 * nt + lg;
        sBfrag[kt][nt][l] = make_uint2(f2tf32(gWc1[c0 * 32 + j]),
                                       f2tf32(gWc1[(c0 + 4) * 32 + j]));
    }
    for (int i = tid; i < 192; i += 128) sZc[i] = fexp10(zlog_c(i));
    __syncthreads();

    // ---- ray setup ----
    float k00 = gK[0], k01 = gK[1], k02 = gK[2];
    float k10 = gK[3], k11 = gK[4], k12 = gK[5];
    float k20 = gK[6], k21 = gK[7], k22 = gK[8];
    float det = k00 * (k11 * k22 - k12 * k21)
              + k01 * (k12 * k20 - k10 * k22)
              + k02 * (k10 * k21 - k11 * k20);
    float id = 1.0f / det;
    float i00 = (k11 * k22 - k12 * k21) * id, i01 = (k02 * k21 - k01 * k22) * id, i02 = (k01 * k12 - k02 * k11) * id;
    float i10 = (k12 * k20 - k10 * k22) * id, i11 = (k00 * k22 - k02 * k20) * id, i12 = (k02 * k10 - k00 * k12) * id;
    float i20 = (k10 * k21 - k11 * k20) * id, i21 = (k01 * k20 - k00 * k21) * id, i22 = (k00 * k11 - k01 * k10) * id;

    float dvx = gw[ray] + 0.5f, dvy = gh[ray] + 0.5f;
    float cx = dvx * i00 + dvy * i01 + i02;
    float cy = dvx * i10 + dvy * i11 + i12;
    float cz = dvx * i20 + dvy * i21 + i22;

    const float* Er = gE + (size_t)ray * 16;
    float ox = Er[3], oy = Er[7], oz = Er[11];
    float rdx = Er[0] * cx + Er[1] * cy + Er[2]  * cz;
    float rdy = Er[4] * cx + Er[5] * cy + Er[6]  * cz;
    float rdz = Er[8] * cx + Er[9] * cy + Er[10] * cz;
    float rn  = sqrtf(rdx * rdx + rdy * rdy + rdz * rdz);
    float irn = __fdividef(1.0f, rn);
    float ndx = rdx * irn, ndy = rdy * irn, ndz = rdz * irn;

    const float bd2v = gbd2[0];

    // per-ray layer1 init: bc1[j] + dir terms (rows 32..34 of Wc1); lane j
    {
        int j = lane;
        float ini = gbc1[j];
        ini = fmaf(ndx, gWc1[1024 + j], ini);
        ini = fmaf(ndy, gWc1[1056 + j], ini);
        ini = fmaf(ndz, gWc1[1088 + j], ini);
        sInit[warp][j] = ini;
    }
    __syncwarp();

    // ---- coarse pass: 6 samples/lane, single pass over density weights ----
    float alpha[6];
    {
        float cpx[6], cpy[6], cpz[6];
#pragma unroll
        for (int q = 0; q < 6; ++q) {
            float zq = sZc[lane * 6 + q];
            cpx[q] = fmaf(rdx, zq, ox);
            cpy[q] = fmaf(rdy, zq, oy);
            cpz[q] = fmaf(rdz, zq, oz);
            mip_scale(cpx[q], cpy[q], cpz[q]);
        }
        float sg[6] = { bd2v, bd2v, bd2v, bd2v, bd2v, bd2v };
#pragma unroll 4
        for (int c = 0; c < 32; ++c) {
            float4 wd = sWd1p[c];
            float v2 = sWd2[c];
#pragma unroll
            for (int q = 0; q < 6; ++q) {
                float t = fmaf(cpx[q], wd.x, fmaf(cpy[q], wd.y, fmaf(cpz[q], wd.z, wd.w)));
                t = fmaxf(t, 0.0f);
                sg[q] = fmaf(t, v2, sg[q]);
            }
        }
#pragma unroll
        for (int q = 0; q < 6; ++q) {
            int s = lane * 6 + q;
            float d = (s < 128) ? 0.0078125f : ((s < 191) ? 0.015625f : 0.0f);
            alpha[q] = 1.0f - fexp(-fsoftplus(sg[q]) * d);
        }
    }

    // ---- transmittance weights (warp multiplicative scan) ----
    float om[6]; float lprod = 1.0f;
#pragma unroll
    for (int q = 0; q < 6; ++q) { om[q] = 1.0f - alpha[q]; lprod *= om[q]; }
    float scanp = lprod;
#pragma unroll
    for (int o = 1; o < 32; o <<= 1) {
        float t = __shfl_up_sync(0xffffffffu, scanp, o);
        if (lane >= o) scanp *= t;
    }
    float T = __shfl_up_sync(0xffffffffu, scanp, 1);
    if (lane == 0) T = 1.0f;
    float wgt[6];
#pragma unroll
    for (int q = 0; q < 6; ++q) { wgt[q] = alpha[q] * T; T *= om[q]; }

    // ---- reweight ----
    float wprev = __shfl_up_sync(0xffffffffu, wgt[5], 1);   if (lane == 0)  wprev = 0.0f;
    float wnext = __shfl_down_sync(0xffffffffu, wgt[0], 1); if (lane == 31) wnext = 0.0f;
    float wr[6]; float lsum = 0.0f;
#pragma unroll
    for (int q = 0; q < 6; ++q) {
        float wm = (q == 0) ? wprev : wgt[q - 1];
        float wp = (q == 5) ? wnext : wgt[q + 1];
        float v = 0.5f * (fmaxf(wm, wgt[q]) + fmaxf(wgt[q], wp)) + (float)(0.02 / 192.0);
        int s = lane * 6 + q;
        v *= (s < 128) ? (float)(128.0 / 192.0) : (float)(64.0 / 192.0);
        wr[q] = v; lsum += v;
    }
    float tot = lsum;
#pragma unroll
    for (int o = 16; o; o >>= 1) tot += __shfl_xor_sync(0xffffffffu, tot, o);
    float itot = __fdividef(1.0f, tot);

    float wn[6]; float ls2 = 0.0f;
#pragma unroll
    for (int q = 0; q < 6; ++q) { wn[q] = wr[q] * itot; ls2 += wn[q]; }
    float scs = ls2;
#pragma unroll
    for (int o = 1; o < 32; o <<= 1) {
        float t = __shfl_up_sync(0xffffffffu, scs, o);
        if (lane >= o) scs += t;
    }
    float base = __shfl_up_sync(0xffffffffu, scs, 1);
    if (lane == 0) base = 0.0f;
    float run = base;
#pragma unroll
    for (int q = 0; q < 6; ++q) { run += wn[q]; sCdf[warp][lane * 6 + q] = run; }
    sCdf[warp][192 + lane] = 1e30f;
    sCdf[warp][224 + lane] = 1e30f;
    __syncwarp();

    const float cdfl = sCdf[warp][1];
    const float cdfh = sCdf[warp][190];

    // ---- importance sampling: unconditional branchless bit-ladder ----
    float zlf[4];
#pragma unroll
    for (int q = 0; q < 4; ++q) {
        int j = (lane << 2) + q;
        float r = tf_uniform((unsigned)(ray * NFINE + j));
        float u = (float)j * 0.0078125f + r * 0.0078125f;
        u = u * (cdfh - cdfl) + cdfl;
        int k = 0;
#pragma unroll
        for (int s = 128; s >= 1; s >>= 1) {
            int cand = k + s;
            if (sCdf[warp][cand] <= u) k = cand;
        }
        float cb = sCdf[warp][k], ca = sCdf[warp][k + 1];
        float tt = __fdividef(u - cb, ca - cb);
        float zb = zmid_c(k), za = zmid_c(k + 1);
        zlf[q] = zb + (za - zb) * tt;
    }

    // ---- fine pass: positions for ALL 4 samples hoisted (MUFU chains overlap) ----
    float px[4], py[4], pz[4];
#pragma unroll
    for (int q = 0; q < 4; ++q) {
        float zq = fexp10(zlf[q]);
        px[q] = fmaf(rdx, zq, ox);
        py[q] = fmaf(rdy, zq, oy);
        pz[q] = fmaf(rdz, zq, oz);
        mip_scale(px[q], py[q], pz[q]);
    }

    const float bc2x = gbc2[0], bc2y = gbc2[1], bc2z = gbc2[2];
    float sig[4], rr[4], rg[4], rb[4];

    // q-invariant init pairs (cols 8nt+2tig, +1)
    float2 iniv[4];
#pragma unroll
    for (int nt = 0; nt < 4; ++nt)
        iniv[nt] = *(const float2*)&sInit[warp][8 * nt + 2 * tig];

#pragma unroll
    for (int q = 0; q < 4; ++q) {
        const int pb = q & 1;               // buffer parity
        float* aT = sT[warp][pb];

        // 1) compute hidden t for own sample; stage tf32 T tile; sigma path fp32
        float sgq = bd2v;
#pragma unroll
        for (int cg = 0; cg < 8; ++cg) {
            uint4 tc;
#pragma unroll
            for (int cc = 0; cc < 4; ++cc) {
                int c = 4 * cg + cc;
                float4 wd = sWd1p[c];
                float t = fmaf(px[q], wd.x, fmaf(py[q], wd.y, fmaf(pz[q], wd.z, wd.w)));
                t = fmaxf(t, 0.0f);
                sgq = fmaf(t, sWd2[c], sgq);
                ((uint32_t*)&tc)[cc] = f2tf32(t);
            }
            *(uint4*)(aT + lane * 32 + 4 * (cg ^ (lane & 7))) = tc;
        }
        sig[q] = fsoftplus(sgq);
        __syncwarp();                        // RAW: T tile

        // 2) GEMM, kt-outer with both m-tiles live
        float d[32];                 // [mt][nt][4]
#pragma unroll
        for (int mt = 0; mt < 2; ++mt)
#pragma unroll
            for (int nt = 0; nt < 4; ++nt) {
                d[16 * mt + 4 * nt + 0] = iniv[nt].x;
                d[16 * mt + 4 * nt + 1] = iniv[nt].y;
                d[16 * mt + 4 * nt + 2] = iniv[nt].x;
                d[16 * mt + 4 * nt + 3] = iniv[nt].y;
            }
        const int sw = 4 * gid;
#pragma unroll
        for (int kt = 0; kt < 4; ++kt) {
            int c0 = (8 * kt + tig) ^ sw;
            int c1 = (8 * kt + tig + 4) ^ sw;
            uint32_t a0 = *(const uint32_t*)(aT + gid * 32 + c0);
            uint32_t a1 = *(const uint32_t*)(aT + (gid + 8) * 32 + c0);
            uint32_t a2 = *(const uint32_t*)(aT + gid * 32 + c1);
            uint32_t a3 = *(const uint32_t*)(aT + (gid + 8) * 32 + c1);
            uint32_t a4 = *(const uint32_t*)(aT + (gid + 16) * 32 + c0);
            uint32_t a5 = *(const uint32_t*)(aT + (gid + 24) * 32 + c0);
            uint32_t a6 = *(const uint32_t*)(aT + (gid + 16) * 32 + c1);
            uint32_t a7 = *(const uint32_t*)(aT + (gid + 24) * 32 + c1);
#pragma unroll
            for (int nt = 0; nt < 4; ++nt) {
                uint2 bp = sBfrag[kt][nt][lane];
                mma_tf32(d + 4 * nt,      a0, a1, a2, a3, bp.x, bp.y);
                mma_tf32(d + 16 + 4 * nt, a4, a5, a6, a7, bp.x, bp.y);
            }
        }

        // 3) d-frag epilogue: relu + Wc2 partial dot (cols 8nt+2tig, +1)
        float part[4][3];
#pragma unroll
        for (int s = 0; s < 4; ++s) { part[s][0] = 0.0f; part[s][1] = 0.0f; part[s][2] = 0.0f; }
#pragma unroll
        for (int mt = 0; mt < 2; ++mt)
#pragma unroll
            for (int nt = 0; nt < 4; ++nt) {
                float h00 = fmaxf(d[16 * mt + 4 * nt + 0], 0.0f);
                float h01 = fmaxf(d[16 * mt + 4 * nt + 1], 0.0f);
                float h10 = fmaxf(d[16 * mt + 4 * nt + 2], 0.0f);
                float h11 = fmaxf(d[16 * mt + 4 * nt + 3], 0.0f);
                int jj = 8 * nt + 2 * tig;
#pragma unroll
                for (int c = 0; c < 3; ++c) {
                    float2 u2 = *(const float2*)&sWc2c[c][jj];
                    part[2 * mt + 0][c] = fmaf(h00, u2.x, fmaf(h01, u2.y, part[2 * mt + 0][c]));
                    part[2 * mt + 1][c] = fmaf(h10, u2.x, fmaf(h11, u2.y, part[2 * mt + 1][c]));
                }
            }

        // 4) tig-group butterfly reduction
#pragma unroll
        for (int s = 0; s < 4; ++s)
#pragma unroll
            for (int c = 0; c < 3; ++c) {
                part[s][c] += __shfl_xor_sync(0xffffffffu, part[s][c], 1);
                part[s][c] += __shfl_xor_sync(0xffffffffu, part[s][c], 2);
            }

        // 5) exchange to sample-owner lane via dedicated parity buffer
        float4* exch = &sEx[warp][pb][0];
        if (tig == 0) {
#pragma unroll
            for (int s = 0; s < 4; ++s) {
                int row = 16 * (s >> 1) + 8 * (s & 1) + gid;
                exch[row] = make_float4(part[s][0], part[s][1], part[s][2], 0.0f);
            }
        }
        __syncwarp();                        // RAW: exchange buffer
        float4 v = exch[lane];
        rr[q] = fsigmoid(v.x + bc2x);
        rg[q] = fsigmoid(v.y + bc2y);
        rb[q] = fsigmoid(v.z + bc2z);
        // no trailing sync: next q uses the other parity buffers
    }

    // ---- fine weights + accumulation ----
    float znx = __shfl_down_sync(0xffffffffu, zlf[0], 1);
    float dl[4];
    dl[0] = zlf[1] - zlf[0];
    dl[1] = zlf[2] - zlf[1];
    dl[2] = zlf[3] - zlf[2];
    dl[3] = (lane == 31) ? 0.0f : (znx - zlf[3]);

    float al[4], om2[4]; float lp = 1.0f;
#pragma unroll
    for (int q = 0; q < 4; ++q) {
        al[q] = 1.0f - fexp(-sig[q] * dl[q]);
        om2[q] = 1.0f - al[q];
        lp *= om2[q];
    }
    float scan2 = lp;
#pragma unroll
    for (int o = 1; o < 32; o <<= 1) {
        float t = __shfl_up_sync(0xffffffffu, scan2, o);
        if (lane >= o) scan2 *= t;
    }
    float T2 = __shfl_up_sync(0xffffffffu, scan2, 1);
    if (lane == 0) T2 = 1.0f;
    float w4[4];
#pragma unroll
    for (int q = 0; q < 4; ++q) { w4[q] = al[q] * T2; T2 *= om2[q]; }

    float ir = 0.0f, ig = 0.0f, ib = 0.0f, ivd = 0.0f, ws = 0.0f;
#pragma unroll
    for (int q = 0; q < 4; ++q) {
        ir = fmaf(w4[q], rr[q], ir);
        ig = fmaf(w4[q], rg[q], ig);
        ib = fmaf(w4[q], rb[q], ib);
        ivd = fmaf(w4[q], fexp10(-zlf[q]), ivd);
        ws  += w4[q];
    }
#pragma unroll
    for (int o = 16; o; o >>= 1) {
        ir  += __shfl_xor_sync(0xffffffffu, ir, o);
        ig  += __shfl_xor_sync(0xffffffffu, ig, o);
        ib  += __shfl_xor_sync(0xffffffffu, ib, o);
        ivd += __shfl_xor_sync(0xffffffffu, ivd, o);
        ws  += __shfl_xor_sync(0xffffffffu, ws, o);
    }

    // ---- stores ----
    *(float4*)(oW + (size_t)ray * NFINE + lane * 4) =
        make_float4(w4[0], w4[1], w4[2], w4[3]);
    *(float4*)(oZ + (size_t)ray * NFINE + lane * 4) =
        make_float4((zlf[0] + 1.0f) * 0.5f, (zlf[1] + 1.0f) * 0.5f,
                    (zlf[2] + 1.0f) * 0.5f, (zlf[3] + 1.0f) * 0.5f);

    if (lane == 0) {
        float oneMw = 1.0f - ws;
        oImg[ray * 3 + 0] = ir + oneMw * gbg[0];
        oImg[ray * 3 + 1] = ig + oneMw * gbg[1];
        oImg[ray * 3 + 2] = ib + oneMw * gbg[2];
        oInv[ray] = ivd;
    }
}

extern "C" void kernel_launch(void* const* d_in, const int* in_sizes, int n_in,
                              void* d_out, int out_size) {
    const float* h   = (const float*)d_in[1];
    const float* w   = (const float*)d_in[2];
    const float* K   = (const float*)d_in[3];
    const float* E   = (const float*)d_in[4];
    const float* bg  = (const float*)d_in[5];
    const float* Wd1 = (const float*)d_in[6];
    const float* bd1 = (const float*)d_in[7];
    const float* Wd2 = (const float*)d_in[8];
    const float* bd2 = (const float*)d_in[9];
    const float* Wc1 = (const float*)d_in[10];
    const float* bc1 = (const float*)d_in[11];
    const float* Wc2 = (const float*)d_in[12];
    const float* bc2 = (const float*)d_in[13];

    float* out   = (float*)d_out;
    float* oImg  = out;
    float* oW    = out + NRAYS * 3;
    float* oZ    = oW + (size_t)NRAYS * NFINE;
    float* oInv  = oZ + (size_t)NRAYS * NFINE;

    nerf_fused<<<NRAYS / 4, 128>>>(h, w, K, E, bg,
                                   Wd1, bd1, Wd2, bd2,
                                   Wc1, bc1, Wc2, bc2,
                                   oImg, oW, oZ, oInv);
}